// round 13
// baseline (speedup 1.0000x reference)
#include <cuda_runtime.h>
#include <cuda_bf16.h>

// MedianFilter1D: k=9 sliding median, replicate padding. x: [2048 rows, 8192] fp32.
//
// R13: R9 math/pipe-split exactly (R12's extra fma conversions REVERTED — they
// lengthened the critical chain and lost 12us). New: 8 consecutive outputs per
// thread-iteration. Two quads share their middle loads: 4 LDS.128 per 8
// outputs instead of 6 (-33% LDS traffic, half the address arith), and the two
// independent quads give natural 2-wide ILP to hide FMNMX chains.
// bounds(256,4): 64-reg budget for the 16-value working set, no spills.

#define ROW_L 8192
#define PAD   4
#define NT    256
#define OPT   8                        // outputs per thread per iteration
#define ITERS (ROW_L / OPT / NT)       // 4

// ---- FMA-pipe compare-swap (sum/|diff| trick, <=1ulp; validated R9). ----
__device__ __forceinline__ void cswap_fma(float& a, float& b) {
    float s  = a + b;
    float d  = a - b;
    float ad = fabsf(d);
    float lo = (s - ad) * 0.5f;
    float hi = (s + ad) * 0.5f;
    a = lo; b = hi;
}

__device__ __forceinline__ void sort3_fma(float& a, float& b, float& c) {
    cswap_fma(a, b);
    cswap_fma(b, c);
    cswap_fma(a, b);
}

// ---- ALU-pipe (FMNMX) helpers. ----
__device__ __forceinline__ float med3(float a, float b, float c) {
    return fmaxf(fminf(a, b), fminf(fmaxf(a, b), c));
}

// One output: FMNMX insert into sorted pair + hoisted reductions. 11 alu ops.
__device__ __forceinline__ float median_out(float x, float p0, float p1,
                                            float mm, float nn,
                                            float p, float qp1) {
    float a0 = fminf(x, p0);
    float m  = fmaxf(x, p0);
    float lo  = fmaxf(a0, mm);
    float mid = fmaxf(p, fminf(qp1, m));
    float hi  = fminf(fmaxf(m, p1), nn);
    return med3(lo, mid, hi);
}

// 4 outputs from 12 consecutive values va|vb|vc (identity validated R2..R12).
__device__ __forceinline__ float4 median4(float4 va, float4 vb, float4 vc) {
    // Middle triples — FMA pipe.
    float b0 = va.w, b1 = vb.x, b2 = vb.y; sort3_fma(b0, b1, b2);  // T1
    float c0 = vb.z, c1 = vb.w, c2 = vc.x; sort3_fma(c0, c1, c2);  // T2
    // Sorted pairs — FMA pipe.
    float s1 = va.y, s2 = va.z; cswap_fma(s1, s2);                 // (v1,v2)
    float t1 = vc.y, t2 = vc.z; cswap_fma(t1, t2);                 // (v9,v10)
    // Hoisted reductions — ALU pipe.
    const float mm  = fmaxf(b0, c0);
    const float nn  = fminf(b2, c2);
    const float p   = fminf(b1, c1);
    const float q   = fmaxf(b1, c1);
    const float qs2 = fminf(q, s2);
    const float qt2 = fminf(q, t2);
    float4 r;
    r.x = median_out(va.x, s1, s2, mm, nn, p, qs2);   // {v0,v1,v2}  +T1+T2
    r.y = median_out(vc.y, s1, s2, mm, nn, p, qs2);   // {v1,v2,v9}  +T1+T2
    r.z = median_out(va.z, t1, t2, mm, nn, p, qt2);   // {v2,v9,v10} +T1+T2
    r.w = median_out(vc.w, t1, t2, mm, nn, p, qt2);   // {v9,v10,v11}+T1+T2
    return r;
}

__global__ __launch_bounds__(NT, 4)
void median9_kernel(const float* __restrict__ x, float* __restrict__ y) {
    __shared__ __align__(16) float s[ROW_L + 2 * PAD];

    const int row = blockIdx.x;
    const float* xr = x + (size_t)row * ROW_L;
    float* yr       = y + (size_t)row * ROW_L;
    const int t = threadIdx.x;

    // ---- Stage row into smem (float4, coalesced). s[PAD + i] = xr[i]. ----
    const float4* x4 = (const float4*)xr;
    #pragma unroll
    for (int j = 0; j < ROW_L / 4 / NT; j++) {
        int i = t + NT * j;
        float4 v = x4[i];
        *(float4*)&s[PAD + 4 * i] = v;
        if (j == 0 && t == 0) {                          // left replicate halo
            s[0] = v.x; s[1] = v.x; s[2] = v.x; s[3] = v.x;
        }
        if (j == (ROW_L / 4 / NT) - 1 && t == NT - 1) {  // right replicate halo
            s[ROW_L + PAD + 0] = v.w;
            s[ROW_L + PAD + 1] = v.w;
            s[ROW_L + PAD + 2] = v.w;
            s[ROW_L + PAD + 3] = v.w;
        }
    }
    __syncthreads();

    // ---- 8 consecutive outputs per iteration from 16 values (4 LDS.128).
    // Outputs o..o+7 need s[o .. o+15]; quad A uses f0f1f2, quad B f1f2f3.
    #pragma unroll
    for (int u = 0; u < ITERS; u++) {
        const int o = OPT * t + OPT * NT * u;        // output base (mult of 8)

        float4 f0 = *(const float4*)&s[o];
        float4 f1 = *(const float4*)&s[o + 4];
        float4 f2 = *(const float4*)&s[o + 8];
        float4 f3 = *(const float4*)&s[o + 12];

        float4 ra = median4(f0, f1, f2);             // outputs o   .. o+3
        float4 rb = median4(f1, f2, f3);             // outputs o+4 .. o+7

        *(float4*)(yr + o)     = ra;
        *(float4*)(yr + o + 4) = rb;
    }
}

extern "C" void kernel_launch(void* const* d_in, const int* in_sizes, int n_in,
                              void* d_out, int out_size) {
    const float* x = (const float*)d_in[0];
    float* y = (float*)d_out;
    const int rows = in_sizes[0] / ROW_L;            // B*C = 2048
    median9_kernel<<<rows, NT>>>(x, y);
}

// round 14
// speedup vs baseline: 1.3420x; 1.3420x over previous
#include <cuda_runtime.h>
#include <cuda_bf16.h>

// MedianFilter1D: k=9 sliding median, replicate padding. x: [2048 rows, 8192] fp32.
//
// R14: warp-autonomous tiles. Each warp stages its own 1032-float slice
// (1024 outputs + 4+4 halo) into private smem, __syncwarp (no CTA barrier
// anywhere), then computes R9's dual-pipe median math at 16B lane stride
// (R13 proved 32B-stride LDS doubles crossbar phases). No warp ever waits
// on another warp's loads -> one load-latency exposure per warp, not the
// CTA max. Math identical to R9 (best: 22.3us kernel, issue 59.9%).

#define ROW_L 8192
#define NT    256
#define WARPS (NT / 32)          // 8
#define WSEG  1024               // outputs per warp
#define WPADF 1040               // slice stride in floats (4160B, 16B-aligned)

// ---- FMA-pipe compare-swap (sum/|diff| trick, <=1ulp; validated R9). ----
__device__ __forceinline__ void cswap_fma(float& a, float& b) {
    float s  = a + b;
    float d  = a - b;
    float ad = fabsf(d);
    float lo = (s - ad) * 0.5f;
    float hi = (s + ad) * 0.5f;
    a = lo; b = hi;
}

__device__ __forceinline__ void sort3_fma(float& a, float& b, float& c) {
    cswap_fma(a, b);
    cswap_fma(b, c);
    cswap_fma(a, b);
}

// ---- ALU-pipe (FMNMX) helpers. ----
__device__ __forceinline__ float med3(float a, float b, float c) {
    return fmaxf(fminf(a, b), fminf(fmaxf(a, b), c));
}

__device__ __forceinline__ float median_out(float x, float p0, float p1,
                                            float mm, float nn,
                                            float p, float qp1) {
    float a0 = fminf(x, p0);
    float m  = fmaxf(x, p0);
    float lo  = fmaxf(a0, mm);
    float mid = fmaxf(p, fminf(qp1, m));
    float hi  = fminf(fmaxf(m, p1), nn);
    return med3(lo, mid, hi);
}

// 4 outputs from 12 consecutive values (identity validated R2..R13).
__device__ __forceinline__ float4 median4(float4 va, float4 vb, float4 vc) {
    float b0 = va.w, b1 = vb.x, b2 = vb.y; sort3_fma(b0, b1, b2);  // T1
    float c0 = vb.z, c1 = vb.w, c2 = vc.x; sort3_fma(c0, c1, c2);  // T2
    float s1 = va.y, s2 = va.z; cswap_fma(s1, s2);                 // (v1,v2)
    float t1 = vc.y, t2 = vc.z; cswap_fma(t1, t2);                 // (v9,v10)
    const float mm  = fmaxf(b0, c0);
    const float nn  = fminf(b2, c2);
    const float p   = fminf(b1, c1);
    const float q   = fmaxf(b1, c1);
    const float qs2 = fminf(q, s2);
    const float qt2 = fminf(q, t2);
    float4 r;
    r.x = median_out(va.x, s1, s2, mm, nn, p, qs2);
    r.y = median_out(vc.y, s1, s2, mm, nn, p, qs2);
    r.z = median_out(va.z, t1, t2, mm, nn, p, qt2);
    r.w = median_out(vc.w, t1, t2, mm, nn, p, qt2);
    return r;
}

__global__ __launch_bounds__(NT, 5)
void median9_kernel(const float* __restrict__ x, float* __restrict__ y) {
    __shared__ __align__(16) float ws[WARPS * WPADF];   // 33.3 KB

    const int row = blockIdx.x;
    const int w   = threadIdx.x >> 5;
    const int l   = threadIdx.x & 31;
    const float* __restrict__ xr = x + ((size_t)row << 13);
    float* __restrict__ yr       = y + ((size_t)row << 13);

    float* slice = &ws[w * WPADF];       // slice[i] = x[WSEG*w - 4 + i]
    const int base = WSEG * w;           // warp's first output in the row

    // ---- Stage: 1024 floats, warp-coalesced float4 (16B lane stride). ----
    const float4* x4 = (const float4*)(xr + base);
    #pragma unroll
    for (int j = 0; j < WSEG / 4 / 32; j++) {           // 8 iters
        int i = l + 32 * j;
        *(float4*)&slice[4 + 4 * i] = x4[i];
    }
    // Halos: clamped global loads (real neighbor data at interior warp
    // boundaries, replicate at true row edges). Lanes 0-7 only.
    if (l < 8) {
        int k  = (l < 4) ? l : (4 + WSEG + (l - 4));    // 0..3 | 1028..1031
        int gi = base - 4 + k;
        gi = min(max(gi, 0), ROW_L - 1);
        slice[k] = xr[gi];
    }
    __syncwarp();                        // warp-local visibility; no BAR.SYNC

    // ---- Compute: 8 quads per lane, 16B lane stride on every LDS.128. ----
    // Lane l, quad u: outputs [base + 4l + 128u, +4); window slice[b..b+11],
    // b = 4l + 128u  (slice is shifted by -4, matching R9 indexing).
    #pragma unroll
    for (int u = 0; u < WSEG / 4 / 32; u++) {           // 8 iters
        const int b = 4 * l + 128 * u;
        float4 va = *(const float4*)&slice[b];
        float4 vb = *(const float4*)&slice[b + 4];
        float4 vc = *(const float4*)&slice[b + 8];
        *(float4*)(yr + base + b) = median4(va, vb, vc);
    }
}

extern "C" void kernel_launch(void* const* d_in, const int* in_sizes, int n_in,
                              void* d_out, int out_size) {
    const float* x = (const float*)d_in[0];
    float* y = (float*)d_out;
    const int rows = in_sizes[0] / ROW_L;               // B*C = 2048
    median9_kernel<<<rows, NT>>>(x, y);
}

// round 15
// speedup vs baseline: 1.3524x; 1.0077x over previous
#include <cuda_runtime.h>
#include <cuda_bf16.h>
#include <cstdint>

// MedianFilter1D: k=9 sliding median, replicate padding. x: [2048 rows, 8192] fp32.
//
// R15: persistent double-buffered kernel. 740 CTAs (one full wave at occ 5)
// grid-stride over 4096 half-row tiles; cp.async loads tile i+1 into the
// alternate smem buffer WHILE computing tile i. Per-CTA load-latency
// exposure drops from once-per-2048-CTAs to once-per-740, steady-state
// loads hide behind ~2000cyc of compute per tile, and wave quantization
// (2.77 waves in R2/R9) disappears. Math = R9's validated dual-pipe split.

#define ROW_L  8192
#define TILE   4096                  // outputs per tile (half row)
#define NT     256
#define BUFLEN 4104                  // 4 halo + 4096 + 4 halo floats
#define GRID   740                   // 148 SMs x 5 CTAs

__device__ __forceinline__ void cp_async16(uint32_t saddr, const void* g) {
    asm volatile("cp.async.cg.shared.global [%0], [%1], 16;\n"
                 :: "r"(saddr), "l"(g) : "memory");
}
__device__ __forceinline__ void cp_async4(uint32_t saddr, const void* g) {
    asm volatile("cp.async.ca.shared.global [%0], [%1], 4;\n"
                 :: "r"(saddr), "l"(g) : "memory");
}
__device__ __forceinline__ void cp_commit() {
    asm volatile("cp.async.commit_group;\n" ::: "memory");
}
template <int N>
__device__ __forceinline__ void cp_wait() {
    asm volatile("cp.async.wait_group %0;\n" :: "n"(N) : "memory");
}

// ---- FMA-pipe compare-swap (sum/|diff| trick, <=1ulp; validated R9+). ----
__device__ __forceinline__ void cswap_fma(float& a, float& b) {
    float s  = a + b;
    float d  = a - b;
    float ad = fabsf(d);
    float lo = (s - ad) * 0.5f;
    float hi = (s + ad) * 0.5f;
    a = lo; b = hi;
}
__device__ __forceinline__ void sort3_fma(float& a, float& b, float& c) {
    cswap_fma(a, b);
    cswap_fma(b, c);
    cswap_fma(a, b);
}

// ---- ALU-pipe (FMNMX) helpers. ----
__device__ __forceinline__ float med3(float a, float b, float c) {
    return fmaxf(fminf(a, b), fminf(fmaxf(a, b), c));
}
__device__ __forceinline__ float median_out(float x, float p0, float p1,
                                            float mm, float nn,
                                            float p, float qp1) {
    float a0 = fminf(x, p0);
    float m  = fmaxf(x, p0);
    float lo  = fmaxf(a0, mm);
    float mid = fmaxf(p, fminf(qp1, m));
    float hi  = fminf(fmaxf(m, p1), nn);
    return med3(lo, mid, hi);
}

// 4 outputs from 12 consecutive values (identity validated R2..R14).
__device__ __forceinline__ float4 median4(float4 va, float4 vb, float4 vc) {
    float b0 = va.w, b1 = vb.x, b2 = vb.y; sort3_fma(b0, b1, b2);  // T1
    float c0 = vb.z, c1 = vb.w, c2 = vc.x; sort3_fma(c0, c1, c2);  // T2
    float s1 = va.y, s2 = va.z; cswap_fma(s1, s2);                 // (v1,v2)
    float t1 = vc.y, t2 = vc.z; cswap_fma(t1, t2);                 // (v9,v10)
    const float mm  = fmaxf(b0, c0);
    const float nn  = fminf(b2, c2);
    const float p   = fminf(b1, c1);
    const float q   = fmaxf(b1, c1);
    const float qs2 = fminf(q, s2);
    const float qt2 = fminf(q, t2);
    float4 r;
    r.x = median_out(va.x, s1, s2, mm, nn, p, qs2);
    r.y = median_out(vc.y, s1, s2, mm, nn, p, qs2);
    r.z = median_out(va.z, t1, t2, mm, nn, p, qt2);
    r.w = median_out(vc.w, t1, t2, mm, nn, p, qt2);
    return r;
}

// Issue all cp.asyncs for one tile into buffer b (one commit group).
// s[b][i] = x_row[halfbase - 4 + i], clamped to [0, ROW_L-1] at row edges.
__device__ __forceinline__ void issue_tile(const float* __restrict__ x,
                                           uint32_t sb_addr, int tile, int t) {
    const int row  = tile >> 1;
    const int half = (tile & 1) << 12;                // 0 or 4096
    const float* __restrict__ xr = x + ((size_t)row << 13);
    // Bulk: 16KB, 4 x 16B per thread, 16B lane stride (coalesced).
    #pragma unroll
    for (int j = 0; j < 4; j++) {
        int e4 = t + NT * j;                          // float4 index 0..1023
        cp_async16(sb_addr + 16u + 16u * (uint32_t)e4, xr + half + 4 * e4);
    }
    // Halos: 8 x 4B with clamped addresses (replicate only at true row edges).
    if (t < 8) {
        int k  = (t < 4) ? t : (4 + TILE + (t - 4));  // dest idx 0..3 | 4100..4103
        int gi = (t < 4) ? (half - 4 + t) : (half + TILE + (t - 4));
        gi = min(max(gi, 0), ROW_L - 1);
        cp_async4(sb_addr + 4u * (uint32_t)k, xr + gi);
    }
    cp_commit();
}

__global__ __launch_bounds__(NT, 5)
void median9_kernel(const float* __restrict__ x, float* __restrict__ y,
                    int ntiles) {
    __shared__ __align__(16) float s[2][BUFLEN];

    const int t = threadIdx.x;
    const uint32_t sb0 = (uint32_t)__cvta_generic_to_shared(&s[0][0]);
    const uint32_t sb1 = (uint32_t)__cvta_generic_to_shared(&s[1][0]);

    int tile = blockIdx.x;
    if (tile >= ntiles) return;

    int b = 0;
    issue_tile(x, sb0, tile, t);                      // prologue load

    while (true) {
        const int next = tile + GRID;
        const bool has_next = (next < ntiles);
        if (has_next) issue_tile(x, b ? sb0 : sb1, next, t);

        if (has_next) cp_wait<1>(); else cp_wait<0>();   // current tile landed
        __syncthreads();

        // ---- Compute current tile from s[b]. 4 quads per thread,
        //      16B lane stride (conflict-free LDS, coalesced STG). ----
        const int row  = tile >> 1;
        const int half = (tile & 1) << 12;
        float* __restrict__ yo = y + ((size_t)row << 13) + half;
        const float* sb = s[b];
        #pragma unroll
        for (int u = 0; u < TILE / 4 / NT; u++) {     // 4 iters
            const int o = 4 * t + 4 * NT * u;         // tile-local quad base
            float4 va = *(const float4*)&sb[o];
            float4 vb = *(const float4*)&sb[o + 4];
            float4 vc = *(const float4*)&sb[o + 8];
            *(float4*)(yo + o) = median4(va, vb, vc);
        }

        if (!has_next) break;
        __syncthreads();     // all warps done reading s[b] before the next
                             // iteration's cp.asyncs overwrite it
        tile = next;
        b ^= 1;
    }
}

extern "C" void kernel_launch(void* const* d_in, const int* in_sizes, int n_in,
                              void* d_out, int out_size) {
    const float* x = (const float*)d_in[0];
    float* y = (float*)d_out;
    const int rows   = in_sizes[0] / ROW_L;           // B*C = 2048
    const int ntiles = rows * (ROW_L / TILE);         // 4096
    median9_kernel<<<GRID, NT>>>(x, y, ntiles);
}